// round 2
// baseline (speedup 1.0000x reference)
#include <cuda_runtime.h>
#include <cstdint>
#include <cstddef>

#define Nn 100000
#define Ee 1600000
#define Hh 128
#define H2 256
#define Gg 512
#define EPS 1e-5f

// ---------------- device scratch (no allocation allowed) ----------------
__device__ __align__(16) float g_h  [(size_t)Nn * Hh];   // conv input h
__device__ __align__(16) float g_agg[(size_t)Nn * Hh];   // neighbor sum
__device__ __align__(16) float g_z1 [(size_t)Nn * H2];   // GEMM1 output (pre-BN)
__device__ __align__(16) float g_y  [(size_t)Nn * Hh];   // GEMM2 output / feats
__device__ __align__(16) float g_vf    [Gg * Hh];
__device__ __align__(16) float g_pooled[Gg * Hh];
__device__ __align__(16) float g_u     [Gg * H2];
__device__ float g_stats1[2 * H2];
__device__ float g_stats2[2 * Hh];
__device__ float g_bnp1  [2 * H2];         // scale | shift
__device__ float g_bnp2  [2 * Hh];
__device__ int   g_counts[Gg];
__device__ int   g_idx64;                  // 1 if indices are int64, 0 if int32

// ---------------- index dtype detection (capture-safe, device side) ------
// int64 little-endian values < N have zero high words -> all odd int32
// words of the buffer are zero. Random int32 indices make that impossible.
__global__ void detect_dtype_kernel(const int* __restrict__ ei32) {
    if (threadIdx.x == 0 && blockIdx.x == 0) {
        int nz = 0;
#pragma unroll
        for (int i = 1; i < 64; i += 2) nz += (ei32[i] != 0);
        g_idx64 = (nz == 0) ? 1 : 0;
    }
}

__device__ __forceinline__ int load_idx(const void* p, size_t i, int is64) {
    return is64 ? (int)((const long long*)p)[i] : ((const int*)p)[i];
}

// ---------------- init: vf broadcast + pooled/counts zero ----------------
__global__ void init_vf_kernel(const float* __restrict__ vn_emb) {
    int idx = blockIdx.x * blockDim.x + threadIdx.x;
    if (idx < Gg * Hh) {
        g_vf[idx] = vn_emb[idx & (Hh - 1)];
        g_pooled[idx] = 0.f;
    }
    if (idx < Gg) g_counts[idx] = 0;
}

__global__ void zero_pool_kernel() {
    int idx = blockIdx.x * blockDim.x + threadIdx.x;
    if (idx < Gg * Hh) g_pooled[idx] = 0.f;
    if (idx < Gg) g_counts[idx] = 0;
}

// ------- prep: h = feats (+ vf[batch]), zero agg + stats -----------------
__global__ void prep_kernel(const float* __restrict__ feats, int use_vf,
                            const void* __restrict__ batch) {
    int idx = blockIdx.x * blockDim.x + threadIdx.x;
    if (idx < 2 * H2) g_stats1[idx] = 0.f;
    if (idx < 2 * Hh) g_stats2[idx] = 0.f;
    if (idx >= Nn * Hh) return;
    float v = feats[idx];
    if (use_vf) {
        int is64 = g_idx64;
        int row = idx >> 7;
        int c   = idx & (Hh - 1);
        v += g_vf[load_idx(batch, row, is64) * Hh + c];
    }
    g_h[idx]   = v;
    g_agg[idx] = 0.f;
}

// ---------------- scatter-add over edges: one warp per edge --------------
__global__ void scatter_kernel(const void* __restrict__ ei) {
    int gw = (blockIdx.x * blockDim.x + threadIdx.x) >> 5;
    if (gw >= Ee) return;
    int is64 = g_idx64;
    int lane = threadIdx.x & 31;
    int s = load_idx(ei, gw, is64);
    int d = load_idx(ei, (size_t)Ee + gw, is64);
    float4 v = *(const float4*)(g_h + (size_t)s * Hh + lane * 4);
    float* dst = g_agg + (size_t)d * Hh + lane * 4;
    asm volatile("red.global.add.v4.f32 [%0], {%1, %2, %3, %4};"
                 :: "l"(dst), "f"(v.x), "f"(v.y), "f"(v.z), "f"(v.w)
                 : "memory");
}

// ---------------- fused SGEMM: 128x128 tile, 8x8 per thread --------------
// MODE 0: A := A + A2                      (GIN: h + agg)
// MODE 1: A := relu(A*scale[k] + shift[k]) (BN1 + ReLU applied on load)
// Epilogue: += bias, store C, accumulate per-column sum/sumsq into stats.
template <int MODE>
__global__ void __launch_bounds__(256)
sgemm_fused(int M, int K, int Ncols,
            const float* __restrict__ A, const float* __restrict__ A2,
            const float* __restrict__ scale, const float* __restrict__ shift,
            const float* __restrict__ W, const float* __restrict__ bias,
            float* __restrict__ C, float* __restrict__ stats) {
    __shared__ float As[8][128];
    __shared__ float Bs[8][128];
    __shared__ float ssum[128], ssq[128];

    const int tid = threadIdx.x;
    const int rowBase = blockIdx.y * 128;
    const int colBase = blockIdx.x * 128;

    const int aRow = tid >> 1;
    const int aCol = (tid & 1) * 4;
    const int bRow = tid >> 5;
    const int bCol = (tid & 31) * 4;
    const int tx = tid & 15;
    const int ty = tid >> 4;

    const int  gRow   = rowBase + aRow;
    const bool aValid = gRow < M;
    const float* Ap  = A + (size_t)gRow * K;
    const float* A2p = (MODE == 0 && aValid) ? (A2 + (size_t)gRow * K) : nullptr;

    float acc[8][8];
#pragma unroll
    for (int i = 0; i < 8; i++)
#pragma unroll
        for (int j = 0; j < 8; j++) acc[i][j] = 0.f;

    for (int kt = 0; kt < K; kt += 8) {
        float4 av = make_float4(0.f, 0.f, 0.f, 0.f);
        if (aValid) {
            av = *(const float4*)(Ap + kt + aCol);
            if (MODE == 0) {
                float4 a2 = *(const float4*)(A2p + kt + aCol);
                av.x += a2.x; av.y += a2.y; av.z += a2.z; av.w += a2.w;
            } else {
                int k0 = kt + aCol;
                av.x = fmaxf(fmaf(av.x, scale[k0 + 0], shift[k0 + 0]), 0.f);
                av.y = fmaxf(fmaf(av.y, scale[k0 + 1], shift[k0 + 1]), 0.f);
                av.z = fmaxf(fmaf(av.z, scale[k0 + 2], shift[k0 + 2]), 0.f);
                av.w = fmaxf(fmaf(av.w, scale[k0 + 3], shift[k0 + 3]), 0.f);
            }
        }
        As[aCol + 0][aRow] = av.x;
        As[aCol + 1][aRow] = av.y;
        As[aCol + 2][aRow] = av.z;
        As[aCol + 3][aRow] = av.w;

        *(float4*)&Bs[bRow][bCol] =
            *(const float4*)(W + (size_t)(kt + bRow) * Ncols + colBase + bCol);
        __syncthreads();

#pragma unroll
        for (int k = 0; k < 8; k++) {
            float rm[8], rn[8];
#pragma unroll
            for (int i = 0; i < 8; i++) rm[i] = As[k][ty * 8 + i];
#pragma unroll
            for (int j = 0; j < 8; j++) rn[j] = Bs[k][tx * 8 + j];
#pragma unroll
            for (int i = 0; i < 8; i++)
#pragma unroll
                for (int j = 0; j < 8; j++)
                    acc[i][j] = fmaf(rm[i], rn[j], acc[i][j]);
        }
        __syncthreads();
    }

    for (int t = tid; t < 128; t += 256) { ssum[t] = 0.f; ssq[t] = 0.f; }
    __syncthreads();

#pragma unroll
    for (int j = 0; j < 8; j++) {
        int col = colBase + tx * 8 + j;
        float bb = bias[col];
        float cs = 0.f, cq = 0.f;
#pragma unroll
        for (int i = 0; i < 8; i++) {
            int row = rowBase + ty * 8 + i;
            if (row < M) {
                float v = acc[i][j] + bb;
                C[(size_t)row * Ncols + col] = v;
                cs += v;
                cq += v * v;
            }
        }
        atomicAdd(&ssum[tx * 8 + j], cs);
        atomicAdd(&ssq[tx * 8 + j], cq);
    }
    __syncthreads();
    for (int t = tid; t < 128; t += 256) {
        atomicAdd(&stats[colBase + t], ssum[t]);
        atomicAdd(&stats[Ncols + colBase + t], ssq[t]);
    }
}

// ---------------- BN finalize: stats -> (scale, shift) -------------------
__global__ void bn_finalize_kernel(const float* __restrict__ stats,
                                   const float* __restrict__ gam,
                                   const float* __restrict__ bet,
                                   int C, float invM, float* __restrict__ params) {
    int c = blockIdx.x * blockDim.x + threadIdx.x;
    if (c >= C) return;
    float mean = stats[c] * invM;
    float var  = stats[C + c] * invM - mean * mean;
    float sc   = gam[c] * rsqrtf(fmaxf(var, 0.f) + EPS);
    params[c]     = sc;
    params[C + c] = bet[c] - mean * sc;
}

// ---------- apply outer BN (+relu) + optional pooling --------------------
__global__ void apply_kernel(const float* __restrict__ y,
                             const float* __restrict__ params, int do_relu,
                             float* __restrict__ out,
                             const void* __restrict__ batch,
                             float* __restrict__ pooled, int* __restrict__ counts) {
    int idx = blockIdx.x * blockDim.x + threadIdx.x;
    if (idx >= Nn * Hh) return;
    int c   = idx & (Hh - 1);
    int row = idx >> 7;
    float v = fmaf(y[idx], params[c], params[Hh + c]);
    if (do_relu) v = fmaxf(v, 0.f);
    out[idx] = v;
    if (pooled) {
        int g = load_idx(batch, row, g_idx64);
        atomicAdd(&pooled[(size_t)g * Hh + c], v);
        if (counts && c == 0) atomicAdd(&counts[g], 1);
    }
}

// ------- virtual-node MLP: one block per output column -------------------
__global__ void vmlp_kernel(const float* __restrict__ in, const float* __restrict__ addv,
                            const float* __restrict__ W, const float* __restrict__ bias,
                            const float* __restrict__ gam, const float* __restrict__ bet,
                            int K, int C, float* __restrict__ out) {
    __shared__ float wcol[H2];
    __shared__ float rs[Gg], rq[Gg];
    int c = blockIdx.x;
    int r = threadIdx.x;  // 512 threads = G rows
    for (int k = r; k < K; k += Gg) wcol[k] = W[(size_t)k * C + c];
    __syncthreads();
    float acc = bias[c];
    const float* ip = in + (size_t)r * K;
    if (addv) {
        const float* ap = addv + (size_t)r * K;
        for (int k = 0; k < K; k++) acc = fmaf(ip[k] + ap[k], wcol[k], acc);
    } else {
        for (int k = 0; k < K; k++) acc = fmaf(ip[k], wcol[k], acc);
    }
    rs[r] = acc;
    rq[r] = acc * acc;
    __syncthreads();
    for (int s = Gg / 2; s > 0; s >>= 1) {
        if (r < s) { rs[r] += rs[r + s]; rq[r] += rq[r + s]; }
        __syncthreads();
    }
    float mean = rs[0] * (1.f / Gg);
    float var  = rq[0] * (1.f / Gg) - mean * mean;
    float v = (acc - mean) * rsqrtf(fmaxf(var, 0.f) + EPS) * gam[c] + bet[c];
    out[(size_t)r * C + c] = fmaxf(v, 0.f);
}

// ---------------- readout ----------------
__global__ void readout_kernel(float* __restrict__ out_read, float* __restrict__ out_vf) {
    int idx = blockIdx.x * blockDim.x + threadIdx.x;
    if (idx >= Gg * Hh) return;
    int g = idx >> 7;
    float cnt = fmaxf((float)g_counts[g], 1.f);
    out_read[idx] = g_pooled[idx] / cnt;
    out_vf[idx]   = g_vf[idx];
}

// ---------------- host orchestration ----------------
extern "C" void kernel_launch(void* const* d_in, const int* in_sizes, int n_in,
                              void* d_out, int out_size) {
    const float* x     = (const float*)d_in[0];
    const void*  ei    = d_in[1];
    const void*  batch = d_in[2];
    // num_graphs may or may not appear as a scalar input at slot 3
    int wi = (in_sizes[3] <= 2) ? 4 : 3;
    const float* conv_w1   = (const float*)d_in[wi + 0];
    const float* conv_b1   = (const float*)d_in[wi + 1];
    const float* conv_bn_g = (const float*)d_in[wi + 2];
    const float* conv_bn_b = (const float*)d_in[wi + 3];
    const float* conv_w2   = (const float*)d_in[wi + 4];
    const float* conv_b2   = (const float*)d_in[wi + 5];
    const float* bn_g      = (const float*)d_in[wi + 6];
    const float* bn_b      = (const float*)d_in[wi + 7];
    const float* vn_emb    = (const float*)d_in[wi + 8];
    const float* vw1       = (const float*)d_in[wi + 9];
    const float* vb1       = (const float*)d_in[wi + 10];
    const float* vbn1g     = (const float*)d_in[wi + 11];
    const float* vbn1b     = (const float*)d_in[wi + 12];
    const float* vw2       = (const float*)d_in[wi + 13];
    const float* vb2       = (const float*)d_in[wi + 14];
    const float* vbn2g     = (const float*)d_in[wi + 15];
    const float* vbn2b     = (const float*)d_in[wi + 16];

    float* out_feats = (float*)d_out;
    float* out_read  = out_feats + (size_t)Nn * Hh;
    float* out_vf    = out_read + Gg * Hh;

    float *p_h, *p_agg, *p_z1, *p_y, *p_vf, *p_pooled, *p_u, *p_s1, *p_s2, *p_b1, *p_b2;
    int* p_cnt;
    cudaGetSymbolAddress((void**)&p_h, g_h);
    cudaGetSymbolAddress((void**)&p_agg, g_agg);
    cudaGetSymbolAddress((void**)&p_z1, g_z1);
    cudaGetSymbolAddress((void**)&p_y, g_y);
    cudaGetSymbolAddress((void**)&p_vf, g_vf);
    cudaGetSymbolAddress((void**)&p_pooled, g_pooled);
    cudaGetSymbolAddress((void**)&p_u, g_u);
    cudaGetSymbolAddress((void**)&p_s1, g_stats1);
    cudaGetSymbolAddress((void**)&p_s2, g_stats2);
    cudaGetSymbolAddress((void**)&p_b1, g_bnp1);
    cudaGetSymbolAddress((void**)&p_b2, g_bnp2);
    cudaGetSymbolAddress((void**)&p_cnt, g_counts);

    const int TPB = 256;
    const int nb_nh = (Nn * Hh + TPB - 1) / TPB;
    const int nb_gh = (Gg * Hh + TPB - 1) / TPB;
    const float invN = 1.f / (float)Nn;

    detect_dtype_kernel<<<1, 32>>>((const int*)ei);
    init_vf_kernel<<<nb_gh, TPB>>>(vn_emb);

    for (int i = 0; i < 3; i++) {
        prep_kernel<<<nb_nh, TPB>>>(i == 0 ? x : p_y, i > 0 ? 1 : 0, batch);
        scatter_kernel<<<(Ee * 32) / TPB, TPB>>>(ei);

        dim3 g1(2, (Nn + 127) / 128);
        sgemm_fused<0><<<g1, 256>>>(Nn, Hh, H2, p_h, p_agg, nullptr, nullptr,
                                    conv_w1 + (size_t)i * Hh * H2, conv_b1 + i * H2,
                                    p_z1, p_s1);
        bn_finalize_kernel<<<1, H2>>>(p_s1, conv_bn_g + i * H2, conv_bn_b + i * H2,
                                      H2, invN, p_b1);

        dim3 g2(1, (Nn + 127) / 128);
        sgemm_fused<1><<<g2, 256>>>(Nn, H2, Hh, p_z1, nullptr, p_b1, p_b1 + H2,
                                    conv_w2 + (size_t)i * H2 * Hh, conv_b2 + i * Hh,
                                    p_y, p_s2);
        bn_finalize_kernel<<<1, Hh>>>(p_s2, bn_g + i * Hh, bn_b + i * Hh,
                                      Hh, invN, p_b2);

        if (i == 0) {
            apply_kernel<<<nb_nh, TPB>>>(p_y, p_b2, 1, p_y, batch, nullptr, nullptr);
        } else if (i == 1) {
            apply_kernel<<<nb_nh, TPB>>>(p_y, p_b2, 1, p_y, batch, p_pooled, nullptr);
            vmlp_kernel<<<H2, Gg>>>(p_pooled, p_vf, vw1, vb1, vbn1g, vbn1b, Hh, H2, p_u);
            vmlp_kernel<<<Hh, Gg>>>(p_u, nullptr, vw2, vb2, vbn2g, vbn2b, H2, Hh, p_vf);
            zero_pool_kernel<<<nb_gh, TPB>>>();
        } else {
            apply_kernel<<<nb_nh, TPB>>>(p_y, p_b2, 0, out_feats, batch, p_pooled, p_cnt);
        }
    }

    readout_kernel<<<nb_gh, TPB>>>(out_read, out_vf);
}

// round 5
// speedup vs baseline: 1.3615x; 1.3615x over previous
#include <cuda_runtime.h>
#include <cuda_bf16.h>
#include <cstdint>
#include <cstddef>

#define Nn 100000
#define Ee 1600000
#define Hh 128
#define H2 256
#define Gg 512
#define EPS 1e-5f

// ---------------- device scratch (no allocation allowed) ----------------
__device__ __align__(16) float g_h  [(size_t)Nn * Hh];
__device__ __align__(16) float g_agg[(size_t)Nn * Hh];
__device__ __align__(16) float g_z1 [(size_t)Nn * H2];
__device__ __align__(16) float g_y  [(size_t)Nn * Hh];
__device__ __align__(16) __nv_bfloat16 g_wt1_hi[H2 * Hh];  // [256 N-rows][128 K]
__device__ __align__(16) __nv_bfloat16 g_wt1_lo[H2 * Hh];
__device__ __align__(16) __nv_bfloat16 g_wt2_hi[Hh * H2];  // [128 N-rows][256 K]
__device__ __align__(16) __nv_bfloat16 g_wt2_lo[Hh * H2];
__device__ __align__(16) float g_vf    [Gg * Hh];
__device__ __align__(16) float g_pooled[Gg * Hh];
__device__ __align__(16) float g_u     [Gg * H2];
__device__ float g_stats1[2 * H2];
__device__ float g_stats2[2 * Hh];
__device__ float g_bnp1  [2 * H2];
__device__ float g_bnp2  [2 * Hh];
__device__ int   g_counts[Gg];
__device__ int   g_idx64;

// ---------------- index dtype detection ----------------
__global__ void detect_dtype_kernel(const int* __restrict__ ei32) {
    if (threadIdx.x == 0 && blockIdx.x == 0) {
        int nz = 0;
#pragma unroll
        for (int i = 1; i < 64; i += 2) nz += (ei32[i] != 0);
        g_idx64 = (nz == 0) ? 1 : 0;
    }
}
__device__ __forceinline__ int load_idx(const void* p, size_t i, int is64) {
    return is64 ? (int)((const long long*)p)[i] : ((const int*)p)[i];
}

// ---------------- misc small kernels ----------------
__global__ void init_vf_kernel(const float* __restrict__ vn_emb) {
    int idx = blockIdx.x * blockDim.x + threadIdx.x;
    if (idx < Gg * Hh) { g_vf[idx] = vn_emb[idx & (Hh - 1)]; g_pooled[idx] = 0.f; }
    if (idx < Gg) g_counts[idx] = 0;
}
__global__ void zero_pool_kernel() {
    int idx = blockIdx.x * blockDim.x + threadIdx.x;
    if (idx < Gg * Hh) g_pooled[idx] = 0.f;
    if (idx < Gg) g_counts[idx] = 0;
}

// prep: h = f(feats) (+ vf[batch]); f = relu(bn) when bnp given; zero agg+stats
__global__ void prep_kernel(const float* __restrict__ feats,
                            const float* __restrict__ bnp,
                            int use_vf, const void* __restrict__ batch) {
    int idx = blockIdx.x * blockDim.x + threadIdx.x;
    if (idx < 2 * H2) g_stats1[idx] = 0.f;
    if (idx < 2 * Hh) g_stats2[idx] = 0.f;
    if (idx >= Nn * Hh) return;
    int row = idx >> 7, c = idx & (Hh - 1);
    float v = feats[idx];
    if (bnp) v = fmaxf(fmaf(v, bnp[c], bnp[Hh + c]), 0.f);
    if (use_vf) v += g_vf[load_idx(batch, row, g_idx64) * Hh + c];
    g_h[idx] = v;
    g_agg[idx] = 0.f;
}

__global__ void scatter_kernel(const void* __restrict__ ei) {
    int gw = (blockIdx.x * blockDim.x + threadIdx.x) >> 5;
    if (gw >= Ee) return;
    int is64 = g_idx64, lane = threadIdx.x & 31;
    int s = load_idx(ei, gw, is64);
    int d = load_idx(ei, (size_t)Ee + gw, is64);
    float4 v = *(const float4*)(g_h + (size_t)s * Hh + lane * 4);
    float* dst = g_agg + (size_t)d * Hh + lane * 4;
    asm volatile("red.global.add.v4.f32 [%0], {%1, %2, %3, %4};"
                 :: "l"(dst), "f"(v.x), "f"(v.y), "f"(v.z), "f"(v.w) : "memory");
}

// ---------------- weight transpose + bf16 split: W[K,Nc] -> Wt[Nc][K] ----
__global__ void convert_w_kernel(const float* __restrict__ W, int K, int Nc,
                                 __nv_bfloat16* __restrict__ hi,
                                 __nv_bfloat16* __restrict__ lo) {
    int idx = blockIdx.x * blockDim.x + threadIdx.x;
    if (idx >= K * Nc) return;
    int k = idx / Nc, n = idx % Nc;
    float v = W[idx];
    __nv_bfloat16 h = __float2bfloat16(v);
    hi[n * K + k] = h;
    lo[n * K + k] = __float2bfloat16(v - __bfloat162float(h));
}

// ---------------- mma.sync bf16 helper ----------------
__device__ __forceinline__ void mma_bf16(float* d, const uint32_t* a,
                                         uint32_t b0, uint32_t b1) {
    asm volatile(
        "mma.sync.aligned.m16n8k16.row.col.f32.bf16.bf16.f32 "
        "{%0,%1,%2,%3}, {%4,%5,%6,%7}, {%8,%9}, {%0,%1,%2,%3};"
        : "+f"(d[0]), "+f"(d[1]), "+f"(d[2]), "+f"(d[3])
        : "r"(a[0]), "r"(a[1]), "r"(a[2]), "r"(a[3]), "r"(b0), "r"(b1));
}
__device__ __forceinline__ uint32_t pack_bf16x2(__nv_bfloat16 lo, __nv_bfloat16 hi) {
    return ((uint32_t)__bfloat16_as_ushort(hi) << 16) | __bfloat16_as_ushort(lo);
}

// ---------------- tensor-core GEMM: C[M,NT] = f(A)[M,K] @ Wt^T -----------
// USE_BN: A := relu(A*scale+shift) on load.   ADD2: A := A + A2 on load.
// Split bf16: A = ah+al, B = bh+bl; acc += ah*bh + ah*bl + al*bh (fp32).
// Epilogue: +bias, store C, per-column sum/sumsq -> global stats atomics.
template <int NT, int MT, int USE_BN, int ADD2>
__global__ void __launch_bounds__(512, 1)
gemm_mma(int M, int K,
         const float* __restrict__ A, const float* __restrict__ A2,
         const float* __restrict__ bnp,
         const __nv_bfloat16* __restrict__ Bt_hi,
         const __nv_bfloat16* __restrict__ Bt_lo,
         const float* __restrict__ bias,
         float* __restrict__ C, float* __restrict__ stats) {
    extern __shared__ __align__(16) char smem[];
    constexpr int SA    = 144;                 // smem row stride bytes (72 bf16 slots)
    constexpr int OF_AH = 0;
    constexpr int OF_AL = 128 * SA;            // 18432
    constexpr int OF_BH = 2 * 128 * SA;        // 36864
    constexpr int OF_BL = OF_BH + NT * SA;
    constexpr int NW    = NT / 64;             // N-warps: 4 (NT=256) or 2 (NT=128)

    const int tid = threadIdx.x, wid = tid >> 5, lane = tid & 31;
    const int g = lane >> 2, tg = lane & 3;
    const int warpM = (wid / NW) * (16 * MT);
    const int warpN = (wid % NW) * 64;
    const int rowBase = blockIdx.x * 128;

    float acc[MT][8][4];
#pragma unroll
    for (int mt = 0; mt < MT; mt++)
#pragma unroll
        for (int nt = 0; nt < 8; nt++)
#pragma unroll
            for (int q = 0; q < 4; q++) acc[mt][nt][q] = 0.f;

    const int nch = K >> 6;
    for (int ch = 0; ch < nch; ch++) {
        const int kb = ch << 6;
        // ---- A chunk: 128 x 64 fp32 -> bf16 hi/lo smem ----
#pragma unroll
        for (int u = tid; u < 2048; u += 512) {
            int r = u >> 4, seg = u & 15;
            int gr = rowBase + r;
            float4 v = make_float4(0.f, 0.f, 0.f, 0.f);
            if (gr < M) {
                v = *(const float4*)(A + (size_t)gr * K + kb + seg * 4);
                if (ADD2) {
                    float4 w = *(const float4*)(A2 + (size_t)gr * K + kb + seg * 4);
                    v.x += w.x; v.y += w.y; v.z += w.z; v.w += w.w;
                }
                if (USE_BN) {
                    int k0 = kb + seg * 4;
                    v.x = fmaxf(fmaf(v.x, bnp[k0 + 0], bnp[K + k0 + 0]), 0.f);
                    v.y = fmaxf(fmaf(v.y, bnp[k0 + 1], bnp[K + k0 + 1]), 0.f);
                    v.z = fmaxf(fmaf(v.z, bnp[k0 + 2], bnp[K + k0 + 2]), 0.f);
                    v.w = fmaxf(fmaf(v.w, bnp[k0 + 3], bnp[K + k0 + 3]), 0.f);
                }
            }
            __nv_bfloat16 hx = __float2bfloat16(v.x), hy = __float2bfloat16(v.y);
            __nv_bfloat16 hz = __float2bfloat16(v.z), hw = __float2bfloat16(v.w);
            uint2 ph, pl;
            ph.x = pack_bf16x2(hx, hy);
            ph.y = pack_bf16x2(hz, hw);
            pl.x = pack_bf16x2(__float2bfloat16(v.x - __bfloat162float(hx)),
                               __float2bfloat16(v.y - __bfloat162float(hy)));
            pl.y = pack_bf16x2(__float2bfloat16(v.z - __bfloat162float(hz)),
                               __float2bfloat16(v.w - __bfloat162float(hw)));
            *(uint2*)(smem + OF_AH + r * SA + seg * 8) = ph;
            *(uint2*)(smem + OF_AL + r * SA + seg * 8) = pl;
        }
        // ---- B chunk: NT x 64 bf16 (pre-split) ----
#pragma unroll
        for (int u = tid; u < NT * 8; u += 512) {
            int r = u >> 3, seg = u & 7;
            *(uint4*)(smem + OF_BH + r * SA + seg * 16) =
                *(const uint4*)(Bt_hi + (size_t)r * K + kb + seg * 8);
            *(uint4*)(smem + OF_BL + r * SA + seg * 16) =
                *(const uint4*)(Bt_lo + (size_t)r * K + kb + seg * 8);
        }
        __syncthreads();

        // ---- compute: 4 ksteps of 16 ----
#pragma unroll
        for (int ks = 0; ks < 4; ks++) {
            const int kbyte = ks * 32 + tg * 4;
            uint32_t ah[MT][4], al[MT][4];
#pragma unroll
            for (int mt = 0; mt < MT; mt++) {
                int r0 = warpM + mt * 16 + g;
                ah[mt][0] = *(const uint32_t*)(smem + OF_AH + r0 * SA + kbyte);
                ah[mt][1] = *(const uint32_t*)(smem + OF_AH + (r0 + 8) * SA + kbyte);
                ah[mt][2] = *(const uint32_t*)(smem + OF_AH + r0 * SA + kbyte + 16);
                ah[mt][3] = *(const uint32_t*)(smem + OF_AH + (r0 + 8) * SA + kbyte + 16);
                al[mt][0] = *(const uint32_t*)(smem + OF_AL + r0 * SA + kbyte);
                al[mt][1] = *(const uint32_t*)(smem + OF_AL + (r0 + 8) * SA + kbyte);
                al[mt][2] = *(const uint32_t*)(smem + OF_AL + r0 * SA + kbyte + 16);
                al[mt][3] = *(const uint32_t*)(smem + OF_AL + (r0 + 8) * SA + kbyte + 16);
            }
#pragma unroll
            for (int nt = 0; nt < 8; nt++) {
                int nr = warpN + nt * 8 + g;
                uint32_t bh0 = *(const uint32_t*)(smem + OF_BH + nr * SA + kbyte);
                uint32_t bh1 = *(const uint32_t*)(smem + OF_BH + nr * SA + kbyte + 16);
                uint32_t bl0 = *(const uint32_t*)(smem + OF_BL + nr * SA + kbyte);
                uint32_t bl1 = *(const uint32_t*)(smem + OF_BL + nr * SA + kbyte + 16);
#pragma unroll
                for (int mt = 0; mt < MT; mt++) {
                    mma_bf16(acc[mt][nt], ah[mt], bh0, bh1);
                    mma_bf16(acc[mt][nt], ah[mt], bl0, bl1);
                    mma_bf16(acc[mt][nt], al[mt], bh0, bh1);
                }
            }
        }
        __syncthreads();
    }

    // ---- epilogue: bias + store + per-column stats ----
    float* ssum = (float*)(smem);
    float* ssq  = (float*)(smem + 1024);
    for (int c = tid; c < NT; c += 512) { ssum[c] = 0.f; ssq[c] = 0.f; }
    __syncthreads();

#pragma unroll
    for (int mt = 0; mt < MT; mt++) {
        int r0 = rowBase + warpM + mt * 16 + g;
        int r1 = r0 + 8;
        bool v0 = r0 < M, v1 = r1 < M;
#pragma unroll
        for (int nt = 0; nt < 8; nt++) {
            int c = warpN + nt * 8 + tg * 2;
            float2 bb = *(const float2*)(bias + c);
            float d0 = acc[mt][nt][0] + bb.x, d1 = acc[mt][nt][1] + bb.y;
            float d2 = acc[mt][nt][2] + bb.x, d3 = acc[mt][nt][3] + bb.y;
            float s0 = 0.f, s1 = 0.f, q0 = 0.f, q1 = 0.f;
            if (v0) {
                float2 o = make_float2(d0, d1);
                *(float2*)(C + (size_t)r0 * NT + c) = o;
                s0 += d0; s1 += d1; q0 += d0 * d0; q1 += d1 * d1;
            }
            if (v1) {
                float2 o = make_float2(d2, d3);
                *(float2*)(C + (size_t)r1 * NT + c) = o;
                s0 += d2; s1 += d3; q0 += d2 * d2; q1 += d3 * d3;
            }
#pragma unroll
            for (int off = 16; off >= 4; off >>= 1) {
                s0 += __shfl_down_sync(0xFFFFFFFFu, s0, off);
                s1 += __shfl_down_sync(0xFFFFFFFFu, s1, off);
                q0 += __shfl_down_sync(0xFFFFFFFFu, q0, off);
                q1 += __shfl_down_sync(0xFFFFFFFFu, q1, off);
            }
            if (lane < 4) {
                atomicAdd(&ssum[c], s0);
                atomicAdd(&ssum[c + 1], s1);
                atomicAdd(&ssq[c], q0);
                atomicAdd(&ssq[c + 1], q1);
            }
        }
    }
    __syncthreads();
    if (tid < NT) {
        atomicAdd(&stats[tid], ssum[tid]);
        atomicAdd(&stats[NT + tid], ssq[tid]);
    }
}

// ---------------- BN finalize ----------------
__global__ void bn_finalize_kernel(const float* __restrict__ stats,
                                   const float* __restrict__ gam,
                                   const float* __restrict__ bet,
                                   int C, float invM, float* __restrict__ params) {
    int c = blockIdx.x * blockDim.x + threadIdx.x;
    if (c >= C) return;
    float mean = stats[c] * invM;
    float var  = stats[C + c] * invM - mean * mean;
    float sc   = gam[c] * rsqrtf(fmaxf(var, 0.f) + EPS);
    params[c]     = sc;
    params[C + c] = bet[c] - mean * sc;
}

// ---------- apply outer BN (+relu) + optional pooling --------------------
__global__ void apply_kernel(const float* __restrict__ y,
                             const float* __restrict__ params, int do_relu,
                             float* __restrict__ out,
                             const void* __restrict__ batch,
                             float* __restrict__ pooled, int* __restrict__ counts) {
    int idx = blockIdx.x * blockDim.x + threadIdx.x;
    if (idx >= Nn * Hh) return;
    int c = idx & (Hh - 1), row = idx >> 7;
    float v = fmaf(y[idx], params[c], params[Hh + c]);
    if (do_relu) v = fmaxf(v, 0.f);
    out[idx] = v;
    if (pooled) {
        int g = load_idx(batch, row, g_idx64);
        atomicAdd(&pooled[(size_t)g * Hh + c], v);
        if (counts && c == 0) atomicAdd(&counts[g], 1);
    }
}

// ---------------- virtual-node MLP ----------------
__global__ void vmlp_kernel(const float* __restrict__ in, const float* __restrict__ addv,
                            const float* __restrict__ W, const float* __restrict__ bias,
                            const float* __restrict__ gam, const float* __restrict__ bet,
                            int K, int C, float* __restrict__ out) {
    __shared__ float wcol[H2];
    __shared__ float rs[Gg], rq[Gg];
    int c = blockIdx.x, r = threadIdx.x;
    for (int k = r; k < K; k += Gg) wcol[k] = W[(size_t)k * C + c];
    __syncthreads();
    float acc = bias[c];
    const float* ip = in + (size_t)r * K;
    if (addv) {
        const float* ap = addv + (size_t)r * K;
        for (int k = 0; k < K; k++) acc = fmaf(ip[k] + ap[k], wcol[k], acc);
    } else {
        for (int k = 0; k < K; k++) acc = fmaf(ip[k], wcol[k], acc);
    }
    rs[r] = acc; rq[r] = acc * acc;
    __syncthreads();
    for (int s = Gg / 2; s > 0; s >>= 1) {
        if (r < s) { rs[r] += rs[r + s]; rq[r] += rq[r + s]; }
        __syncthreads();
    }
    float mean = rs[0] * (1.f / Gg);
    float var  = rq[0] * (1.f / Gg) - mean * mean;
    float v = (acc - mean) * rsqrtf(fmaxf(var, 0.f) + EPS) * gam[c] + bet[c];
    out[(size_t)r * C + c] = fmaxf(v, 0.f);
}

// ---------------- readout ----------------
__global__ void readout_kernel(float* __restrict__ out_read, float* __restrict__ out_vf) {
    int idx = blockIdx.x * blockDim.x + threadIdx.x;
    if (idx >= Gg * Hh) return;
    int g = idx >> 7;
    float cnt = fmaxf((float)g_counts[g], 1.f);
    out_read[idx] = g_pooled[idx] / cnt;
    out_vf[idx]   = g_vf[idx];
}

// ---------------- host orchestration ----------------
extern "C" void kernel_launch(void* const* d_in, const int* in_sizes, int n_in,
                              void* d_out, int out_size) {
    const float* x     = (const float*)d_in[0];
    const void*  ei    = d_in[1];
    const void*  batch = d_in[2];
    int wi = (in_sizes[3] <= 2) ? 4 : 3;
    const float* conv_w1   = (const float*)d_in[wi + 0];
    const float* conv_b1   = (const float*)d_in[wi + 1];
    const float* conv_bn_g = (const float*)d_in[wi + 2];
    const float* conv_bn_b = (const float*)d_in[wi + 3];
    const float* conv_w2   = (const float*)d_in[wi + 4];
    const float* conv_b2   = (const float*)d_in[wi + 5];
    const float* bn_g      = (const float*)d_in[wi + 6];
    const float* bn_b      = (const float*)d_in[wi + 7];
    const float* vn_emb    = (const float*)d_in[wi + 8];
    const float* vw1       = (const float*)d_in[wi + 9];
    const float* vb1       = (const float*)d_in[wi + 10];
    const float* vbn1g     = (const float*)d_in[wi + 11];
    const float* vbn1b     = (const float*)d_in[wi + 12];
    const float* vw2       = (const float*)d_in[wi + 13];
    const float* vb2       = (const float*)d_in[wi + 14];
    const float* vbn2g     = (const float*)d_in[wi + 15];
    const float* vbn2b     = (const float*)d_in[wi + 16];

    float* out_feats = (float*)d_out;
    float* out_read  = out_feats + (size_t)Nn * Hh;
    float* out_vf    = out_read + Gg * Hh;

    float *p_h, *p_agg, *p_z1, *p_y, *p_vf, *p_pooled, *p_u, *p_s1, *p_s2, *p_b1, *p_b2;
    __nv_bfloat16 *p_w1h, *p_w1l, *p_w2h, *p_w2l;
    int* p_cnt;
    cudaGetSymbolAddress((void**)&p_h, g_h);
    cudaGetSymbolAddress((void**)&p_agg, g_agg);
    cudaGetSymbolAddress((void**)&p_z1, g_z1);
    cudaGetSymbolAddress((void**)&p_y, g_y);
    cudaGetSymbolAddress((void**)&p_vf, g_vf);
    cudaGetSymbolAddress((void**)&p_pooled, g_pooled);
    cudaGetSymbolAddress((void**)&p_u, g_u);
    cudaGetSymbolAddress((void**)&p_s1, g_stats1);
    cudaGetSymbolAddress((void**)&p_s2, g_stats2);
    cudaGetSymbolAddress((void**)&p_b1, g_bnp1);
    cudaGetSymbolAddress((void**)&p_b2, g_bnp2);
    cudaGetSymbolAddress((void**)&p_cnt, g_counts);
    cudaGetSymbolAddress((void**)&p_w1h, g_wt1_hi);
    cudaGetSymbolAddress((void**)&p_w1l, g_wt1_lo);
    cudaGetSymbolAddress((void**)&p_w2h, g_wt2_hi);
    cudaGetSymbolAddress((void**)&p_w2l, g_wt2_lo);

    const int TPB = 256;
    const int nb_nh = (Nn * Hh + TPB - 1) / TPB;
    const int nb_gh = (Gg * Hh + TPB - 1) / TPB;
    const int nTiles = (Nn + 127) / 128;
    const float invN = 1.f / (float)Nn;
    const int SMEM1 = 2 * 128 * 144 + 2 * H2 * 144;  // 110592
    const int SMEM2 = 2 * 128 * 144 + 2 * Hh * 144;  //  73728

    cudaFuncSetAttribute(gemm_mma<H2, 2, 0, 1>,
                         cudaFuncAttributeMaxDynamicSharedMemorySize, SMEM1);
    cudaFuncSetAttribute(gemm_mma<Hh, 1, 1, 0>,
                         cudaFuncAttributeMaxDynamicSharedMemorySize, SMEM2);

    detect_dtype_kernel<<<1, 32>>>((const int*)ei);
    init_vf_kernel<<<nb_gh, TPB>>>(vn_emb);

    for (int i = 0; i < 3; i++) {
        convert_w_kernel<<<(Hh * H2 + TPB - 1) / TPB, TPB>>>(
            conv_w1 + (size_t)i * Hh * H2, Hh, H2, p_w1h, p_w1l);
        convert_w_kernel<<<(H2 * Hh + TPB - 1) / TPB, TPB>>>(
            conv_w2 + (size_t)i * H2 * Hh, H2, Hh, p_w2h, p_w2l);

        // layer input: i=0 raw x; i=1 fold layer-0 outer BN+ReLU here; i=2 y is BN'd
        prep_kernel<<<nb_nh, TPB>>>(i == 0 ? x : p_y,
                                    (i == 1) ? p_b2 : nullptr,
                                    i > 0 ? 1 : 0, batch);
        scatter_kernel<<<(Ee * 32) / TPB, TPB>>>(ei);

        gemm_mma<H2, 2, 0, 1><<<nTiles, 512, SMEM1>>>(
            Nn, Hh, p_h, p_agg, nullptr, p_w1h, p_w1l,
            conv_b1 + i * H2, p_z1, p_s1);
        bn_finalize_kernel<<<1, H2>>>(p_s1, conv_bn_g + i * H2, conv_bn_b + i * H2,
                                      H2, invN, p_b1);

        gemm_mma<Hh, 1, 1, 0><<<nTiles, 512, SMEM2>>>(
            Nn, H2, p_z1, nullptr, p_b1, p_w2h, p_w2l,
            conv_b2 + i * Hh, p_y, p_s2);
        bn_finalize_kernel<<<1, Hh>>>(p_s2, bn_g + i * Hh, bn_b + i * Hh,
                                      Hh, invN, p_b2);

        if (i == 1) {
            apply_kernel<<<nb_nh, TPB>>>(p_y, p_b2, 1, p_y, batch, p_pooled, nullptr);
            vmlp_kernel<<<H2, Gg>>>(p_pooled, p_vf, vw1, vb1, vbn1g, vbn1b, Hh, H2, p_u);
            vmlp_kernel<<<Hh, Gg>>>(p_u, nullptr, vw2, vb2, vbn2g, vbn2b, H2, Hh, p_vf);
            zero_pool_kernel<<<nb_gh, TPB>>>();
        } else if (i == 2) {
            apply_kernel<<<nb_nh, TPB>>>(p_y, p_b2, 0, out_feats, batch, p_pooled, p_cnt);
        }
        // i == 0: outer BN folded into next layer's prep
    }

    readout_kernel<<<nb_gh, TPB>>>(out_read, out_vf);
}